// round 9
// baseline (speedup 1.0000x reference)
#include <cuda_runtime.h>

#define B 128
#define K 17
#define HW 9216          // 96*96
#define NVEC (HW/4)      // 2304
#define TOPK 8
#define THREADS1 256
#define WARPS_PER_BLK (THREADS1/32)
#define NBLOCKS (B * K)                  // 2176
#define NWARPS_TOTAL (NBLOCKS * WARPS_PER_BLK)   // 17408
#define VEC_PER_WARP (NVEC / WARPS_PER_BLK)      // 288

__device__ float g_per_joint[B * K];     // zero-init at load; reset by tail
__device__ unsigned int g_counter = 0;

__global__ void __launch_bounds__(THREADS1, 4)
mse_ohkm_warp_kernel(const float* __restrict__ pred,
                     const float* __restrict__ gt,
                     const float* __restrict__ tw,
                     float* __restrict__ out) {
    const int bk   = blockIdx.x;
    const int lane = threadIdx.x & 31;
    const int wid  = threadIdx.x >> 5;

    const float4* __restrict__ p =
        reinterpret_cast<const float4*>(pred + (size_t)bk * HW) + wid * VEC_PER_WARP;
    const float4* __restrict__ g =
        reinterpret_cast<const float4*>(gt   + (size_t)bk * HW) + wid * VEC_PER_WARP;

    float acc = 0.0f;
    #pragma unroll
    for (int j = 0; j < VEC_PER_WARP / 32; j++) {   // 9 iterations
        const int i = lane + j * 32;
        float4 a = p[i];
        float4 b = g[i];
        float d0 = a.x - b.x;
        float d1 = a.y - b.y;
        float d2 = a.z - b.z;
        float d3 = a.w - b.w;
        acc += d0 * d0 + d1 * d1 + d2 * d2 + d3 * d3;
    }

    // warp-local reduce — NO block sync anywhere
    #pragma unroll
    for (int off = 16; off > 0; off >>= 1)
        acc += __shfl_down_sync(0xFFFFFFFFu, acc, off);

    unsigned int old = 0xFFFFFFFFu;
    if (lane == 0) {
        const float w = tw[bk];
        // fire-and-forget accumulation (REDG, no return value used)
        atomicAdd(&g_per_joint[bk], acc * w * w * (1.0f / (float)HW));
        // release-atomic orders the REDG above (same thread) before the count
        asm volatile("atom.add.release.gpu.global.u32 %0, [%1], 1;"
                     : "=r"(old) : "l"(&g_counter) : "memory");
    }
    // broadcast counter value to the whole warp
    old = __shfl_sync(0xFFFFFFFFu, old, 0);
    if (old != (unsigned int)(NWARPS_TOTAL - 1)) return;

    // ---- single last WARP: OHKM top-k over all B samples (L2-hot) ----
    asm volatile("fence.acq_rel.gpu;" ::: "memory");

    float total = 0.0f;
    #pragma unroll
    for (int q = 0; q < B / 32; q++) {          // 4 samples per lane
        const int b = lane + q * 32;
        const float* row = &g_per_joint[b * K];

        float t[TOPK];
        #pragma unroll
        for (int j = 0; j < TOPK; j++) t[j] = -3.4e38f;

        #pragma unroll
        for (int i = 0; i < K; i++) {
            float x = __ldcg(&row[i]);
            #pragma unroll
            for (int j = 0; j < TOPK; j++) {
                float o = t[j];
                bool gtp = x > o;
                t[j] = gtp ? x : o;
                x    = gtp ? o : x;
            }
        }
        #pragma unroll
        for (int j = 0; j < TOPK; j++) total += t[j];
    }

    // warp reduce the 32 partial sums
    #pragma unroll
    for (int off = 16; off > 0; off >>= 1)
        total += __shfl_down_sync(0xFFFFFFFFu, total, off);

    if (lane == 0)
        out[0] = total * (1.0f / (float)(B * TOPK));

    // reset accumulators for the next graph replay (visible at kernel end)
    float4 z = make_float4(0.f, 0.f, 0.f, 0.f);
    float4* pj4 = reinterpret_cast<float4*>(g_per_joint);
    #pragma unroll
    for (int i = lane; i < (B * K) / 4; i += 32)
        pj4[i] = z;
    if (lane == 0) g_counter = 0u;
}

extern "C" void kernel_launch(void* const* d_in, const int* in_sizes, int n_in,
                              void* d_out, int out_size) {
    const float* pred = (const float*)d_in[0];   // output [B,K,H,W]
    const float* gt   = (const float*)d_in[1];   // target [B,K,H,W]
    const float* tw   = (const float*)d_in[2];   // target_weight [B,K,1]
    float* out = (float*)d_out;

    mse_ohkm_warp_kernel<<<NBLOCKS, THREADS1>>>(pred, gt, tw, out);
}